// round 7
// baseline (speedup 1.0000x reference)
#include <cuda_runtime.h>
#include <cuda_bf16.h>
#include <cstdint>

#define NMAX 50000
#define EMAX 800000
#define D 128

// ---------------- f32x2 packed helpers ----------------
#define FMA2(d, a, b) \
    asm("fma.rn.f32x2 %0, %1, %2, %0;" : "+l"(d) : "l"(a), "l"(b))

__device__ __forceinline__ unsigned long long pk(float lo, float hi) {
    unsigned long long r;
    asm("mov.b64 %0, {%1, %2};" : "=l"(r) : "f"(lo), "f"(hi));
    return r;
}
__device__ __forceinline__ float2 upk(unsigned long long v) {
    float lo, hi;
    asm("mov.b64 {%0, %1}, %2;" : "=f"(lo), "=f"(hi) : "l"(v));
    return make_float2(lo, hi);
}

// ---------------- device scratch ----------------
__device__ float g_xn[NMAX * D];
__device__ float g_xw1[NMAX * 32];
__device__ float g_t2[NMAX * 4];
__device__ float g_dinv1[NMAX];
__device__ int   g_deg1[NMAX];
__device__ int   g_off[NMAX + 1];
__device__ int   g_cursor[NMAX];
__device__ int   g_src[EMAX];
__device__ float g_eap[(size_t)EMAX * 16];
__device__ float g_dinvm[NMAX];
__device__ unsigned char g_flags[NMAX];
__device__ float g_xw[NMAX * D];        // xn @ conv_w (UNscaled)

// ---------------- kernels ----------------

__global__ void k_init(int n) {
    int i = blockIdx.x * blockDim.x + threadIdx.x;
    if (i < n) g_deg1[i] = 0;
}

__global__ void k_deg1(const int* __restrict__ ei, int e_cnt) {
    int base = (blockIdx.x * blockDim.x + threadIdx.x) * 4;
    int d[4];
    #pragma unroll
    for (int j = 0; j < 4; j++) {
        int e = base + j;
        d[j] = (e < e_cnt) ? ei[e_cnt + e] : -1;
    }
    #pragma unroll
    for (int j = 0; j < 4; j++)
        if (d[j] >= 0) atomicAdd(&g_deg1[d[j]], 1);
}

// Merged: block 0 = exclusive scan; blocks 1.. = LayerNorm + layer-1 projections.
__global__ __launch_bounds__(1024) void k_scan_ln(
    const float* __restrict__ x, const float* __restrict__ ln_g, const float* __restrict__ ln_b,
    const float* __restrict__ ia1_w, const float* __restrict__ oa1_w, int n, int e_cnt)
{
    __shared__ int sp[1024];
    __shared__ float sW[D * 32];
    __shared__ float sxn[32][D];
    int tid = threadIdx.x;

    if (blockIdx.x == 0) {
        int chunk = (n + 1023) / 1024;
        int beg = tid * chunk;
        int end = min(beg + chunk, n);
        int s = 0;
        for (int i = beg; i < end; i++) s += g_deg1[i];
        sp[tid] = s;
        __syncthreads();
        for (int o = 1; o < 1024; o <<= 1) {
            int v = (tid >= o) ? sp[tid - o] : 0;
            __syncthreads();
            sp[tid] += v;
            __syncthreads();
        }
        int run = (tid > 0) ? sp[tid - 1] : 0;
        for (int i = beg; i < end; i++) {
            int dg = g_deg1[i];
            g_off[i] = run;
            g_cursor[i] = run;
            g_dinv1[i] = rsqrtf((float)dg + 1.0f);
            run += dg;
        }
        if (tid == 1023) g_off[n] = e_cnt;
        return;
    }

    for (int i = tid; i < D * 32; i += 1024) {
        int k = i >> 5, j = i & 31;
        sW[i] = (j < 16) ? ia1_w[k * 16 + j] : oa1_w[k * 16 + (j - 16)];
    }
    __syncthreads();
    int warp = tid >> 5, lane = tid & 31;
    int nwarps = (gridDim.x - 1) * 32;
    for (int v = (blockIdx.x - 1) * 32 + warp; v < n; v += nwarps) {
        float4 xv = ((const float4*)(x + (size_t)v * D))[lane];
        float s1 = xv.x + xv.y + xv.z + xv.w;
        float s2 = xv.x * xv.x + xv.y * xv.y + xv.z * xv.z + xv.w * xv.w;
        #pragma unroll
        for (int o = 16; o; o >>= 1) {
            s1 += __shfl_xor_sync(0xffffffffu, s1, o);
            s2 += __shfl_xor_sync(0xffffffffu, s2, o);
        }
        float mu = s1 * (1.f / 128.f);
        float var = s2 * (1.f / 128.f) - mu * mu;
        float rs = rsqrtf(var + 1e-5f);
        float4 g4 = ((const float4*)ln_g)[lane];
        float4 b4 = ((const float4*)ln_b)[lane];
        float4 o4;
        o4.x = (xv.x - mu) * rs * g4.x + b4.x;
        o4.y = (xv.y - mu) * rs * g4.y + b4.y;
        o4.z = (xv.z - mu) * rs * g4.z + b4.z;
        o4.w = (xv.w - mu) * rs * g4.w + b4.w;
        ((float4*)(g_xn + (size_t)v * D))[lane] = o4;
        ((float4*)sxn[warp])[lane] = o4;
        __syncwarp();
        float dinv = rsqrtf((float)g_deg1[v] + 1.0f);
        float acc = 0.f;
        const float* sx = sxn[warp];
        #pragma unroll 16
        for (int k = 0; k < D; k++) acc = fmaf(sx[k], sW[k * 32 + lane], acc);
        g_xw1[v * 32 + lane] = acc * dinv;
        __syncwarp();
    }
}

// CSR fill + edge_attr permutation; 4 edges per thread for MLP.
__global__ __launch_bounds__(256) void k_fill(const int* __restrict__ ei,
                                              const float* __restrict__ ea, int e_cnt)
{
    int base = (blockIdx.x * blockDim.x + threadIdx.x) * 4;
    int s[4], d[4], pos[4];
    #pragma unroll
    for (int j = 0; j < 4; j++) {
        int e = base + j;
        if (e < e_cnt) { s[j] = ei[e]; d[j] = ei[e_cnt + e]; }
        else           { s[j] = -1;    d[j] = 0; }
    }
    #pragma unroll
    for (int j = 0; j < 4; j++)
        pos[j] = (s[j] >= 0) ? atomicAdd(&g_cursor[d[j]], 1) : 0;
    #pragma unroll
    for (int j = 0; j < 4; j++) {
        if (s[j] < 0) continue;
        int e = base + j;
        g_src[pos[j]] = s[j];
        const float4* a = (const float4*)(ea + (size_t)e * 16);
        float4 a0 = a[0], a1 = a[1], a2 = a[2], a3 = a[3];
        float4* o = (float4*)(g_eap + (size_t)pos[j] * 16);
        o[0] = a0; o[1] = a1; o[2] = a2; o[3] = a3;
    }
}

// GEMM xw = xn @ conv_w (f32x2 packed, unscaled). 64 rows x 128 cols per block.
__global__ __launch_bounds__(256) void k_gemm(const float* __restrict__ conv_w, int n)
{
    __shared__ float sA[64][32];
    __shared__ ulonglong2 sB[16 * 2 * 32];
    float* sBf = (float*)sB;
    int tid = threadIdx.x;
    int lane = tid & 31, warp = tid >> 5;
    int row0 = blockIdx.x * 64, rb = warp * 8;
    unsigned long long acc[8][4];
    #pragma unroll
    for (int r = 0; r < 8; r++)
        #pragma unroll
        for (int c = 0; c < 4; c++) acc[r][c] = 0ull;

    for (int kc = 0; kc < D; kc += 32) {
        for (int i = tid; i < 1024; i += 256) {
            int kk = i >> 5, c = i & 31;
            float4 w = ((const float4*)(conv_w + (size_t)(kc + kk) * D))[c];
            int p = kk >> 1, par = kk & 1;
            int b0i = (((p * 2 + 0) * 32 + c) << 2);
            int b1i = (((p * 2 + 1) * 32 + c) << 2);
            sBf[b0i + par]     = w.x;
            sBf[b0i + 2 + par] = w.y;
            sBf[b1i + par]     = w.z;
            sBf[b1i + 2 + par] = w.w;
        }
        for (int i = tid; i < 512; i += 256) {
            int r = i >> 3, c4 = i & 7;
            float4 vv = make_float4(0.f, 0.f, 0.f, 0.f);
            if (row0 + r < n)
                vv = ((const float4*)(g_xn + (size_t)(row0 + r) * D + kc))[c4];
            sA[r][c4 * 4 + 0] = vv.x; sA[r][c4 * 4 + 1] = vv.y;
            sA[r][c4 * 4 + 2] = vv.z; sA[r][c4 * 4 + 3] = vv.w;
        }
        __syncthreads();
        #pragma unroll
        for (int p = 0; p < 16; p++) {
            ulonglong2 b0 = sB[(p * 2 + 0) * 32 + lane];
            ulonglong2 b1 = sB[(p * 2 + 1) * 32 + lane];
            #pragma unroll
            for (int r = 0; r < 8; r++) {
                unsigned long long ap = *(const unsigned long long*)&sA[rb + r][2 * p];
                FMA2(acc[r][0], ap, b0.x);
                FMA2(acc[r][1], ap, b0.y);
                FMA2(acc[r][2], ap, b1.x);
                FMA2(acc[r][3], ap, b1.y);
            }
        }
        __syncthreads();
    }
    #pragma unroll
    for (int r = 0; r < 8; r++) {
        int v = row0 + rb + r;
        if (v < n) {
            float2 u0 = upk(acc[r][0]), u1 = upk(acc[r][1]);
            float2 u2 = upk(acc[r][2]), u3 = upk(acc[r][3]);
            float4 o = make_float4(u0.x + u0.y, u1.x + u1.y, u2.x + u2.y, u3.x + u3.y);
            ((float4*)(g_xw + (size_t)v * D))[lane] = o;
        }
    }
}

// CSR gather of layer-1 messages + finalize h + layer-2 projection.
__global__ __launch_bounds__(256) void k_gather1(
    const float* __restrict__ ia1_b, const float* __restrict__ oa1_b,
    const float* __restrict__ ia2_w, const float* __restrict__ oa2_w, int n)
{
    int v = blockIdx.x * 8 + (threadIdx.x >> 5);
    if (v >= n) return;
    int lane = threadIdx.x & 31;
    int beg = g_off[v], end = g_off[v + 1];
    float acc = 0.f;
    int e = beg;
    for (; e + 8 <= end; e += 8) {
        float t0 = 0.f, t1 = 0.f;
        #pragma unroll
        for (int j = 0; j < 8; j += 2) {
            int s0 = g_src[e + j], s1 = g_src[e + j + 1];
            t0 += g_xw1[s0 * 32 + lane];
            t1 += g_xw1[s1 * 32 + lane];
        }
        acc += t0 + t1;
    }
    for (; e < end; e++) acc += g_xw1[g_src[e] * 32 + lane];

    float dinv = g_dinv1[v];
    float bias = (lane < 16) ? ia1_b[lane] : oa1_b[lane - 16];
    float h = fmaf(dinv, acc, fmaf(g_xw1[v * 32 + lane], dinv, bias));
    h = fmaxf(h, 0.f);
    float w0 = (lane < 16) ? ia2_w[lane * 2] : oa2_w[(lane - 16) * 2];
    float w1 = (lane < 16) ? ia2_w[lane * 2 + 1] : oa2_w[(lane - 16) * 2 + 1];
    float p0 = h * w0, p1 = h * w1;
    #pragma unroll
    for (int o = 8; o; o >>= 1) {
        p0 += __shfl_xor_sync(0xffffffffu, p0, o);
        p1 += __shfl_xor_sync(0xffffffffu, p1, o);
    }
    if (lane == 0)  { g_t2[v * 4 + 0] = p0 * dinv; g_t2[v * 4 + 1] = p1 * dinv; }
    if (lane == 16) { g_t2[v * 4 + 2] = p0 * dinv; g_t2[v * 4 + 3] = p1 * dinv; }
}

// CSR gather of layer-2 messages + gumbel decision.
__global__ __launch_bounds__(256) void k_gather2(
    const float* __restrict__ u_in, const float* __restrict__ u_out,
    const float* __restrict__ ia2_b, const float* __restrict__ oa2_b, int n)
{
    int v = blockIdx.x * 8 + (threadIdx.x >> 5);
    if (v >= n) return;
    int lane = threadIdx.x & 31;
    int beg = g_off[v], end = g_off[v + 1];
    float4 a = make_float4(0.f, 0.f, 0.f, 0.f);
    for (int e = beg + lane; e < end; e += 32) {
        int s = g_src[e];
        float4 t = *(const float4*)(g_t2 + (size_t)s * 4);
        a.x += t.x; a.y += t.y; a.z += t.z; a.w += t.w;
    }
    #pragma unroll
    for (int o = 16; o; o >>= 1) {
        a.x += __shfl_xor_sync(0xffffffffu, a.x, o);
        a.y += __shfl_xor_sync(0xffffffffu, a.y, o);
        a.z += __shfl_xor_sync(0xffffffffu, a.z, o);
        a.w += __shfl_xor_sync(0xffffffffu, a.w, o);
    }
    if (lane == 0) {
        float dinv = g_dinv1[v];
        float li0 = fmaf(dinv, a.x, g_t2[v * 4 + 0] * dinv) + ia2_b[0];
        float li1 = fmaf(dinv, a.y, g_t2[v * 4 + 1] * dinv) + ia2_b[1];
        float lo0 = fmaf(dinv, a.z, g_t2[v * 4 + 2] * dinv) + oa2_b[0];
        float lo1 = fmaf(dinv, a.w, g_t2[v * 4 + 3] * dinv) + oa2_b[1];
        float gi0 = -logf(-logf(u_in[v * 2 + 0] + 1e-10f) + 1e-10f);
        float gi1 = -logf(-logf(u_in[v * 2 + 1] + 1e-10f) + 1e-10f);
        float go0 = -logf(-logf(u_out[v * 2 + 0] + 1e-10f) + 1e-10f);
        float go1 = -logf(-logf(u_out[v * 2 + 1] + 1e-10f) + 1e-10f);
        int in0  = (li0 + gi0 >= li1 + gi1) ? 1 : 0;
        int out0 = (lo0 + go0 >= lo1 + go1) ? 1 : 0;
        g_flags[v] = (unsigned char)(in0 | (out0 << 1));
    }
}

// weighted in-degree of main conv via CSR + flags, then dinvm.
__global__ __launch_bounds__(256) void k_degm(int n) {
    int v = blockIdx.x * 8 + (threadIdx.x >> 5);
    if (v >= n) return;
    int lane = threadIdx.x & 31;
    int beg = g_off[v], end = g_off[v + 1];
    int cnt = 0;
    for (int e = beg + lane; e < end; e += 32)
        cnt += (g_flags[g_src[e]] >> 1) & 1;
    #pragma unroll
    for (int o = 16; o; o >>= 1) cnt += __shfl_xor_sync(0xffffffffu, cnt, o);
    if (lane == 0) {
        int myin = g_flags[v] & 1;
        g_dinvm[v] = rsqrtf((float)(myin ? cnt : 0) + 1.0f);
    }
}

// Final fused pass, specialized on myin (inactive dst skips all msg loads).
__global__ __launch_bounds__(256) void k_final(const float* __restrict__ ep_w,
                                               const float* __restrict__ ep_b,
                                               const float* __restrict__ conv_b,
                                               float* __restrict__ out, int n)
{
    int tid = threadIdx.x, lane = tid & 31;
    int v = blockIdx.x * 8 + (tid >> 5);
    if (v >= n) return;

    unsigned long long wkp[8][4];
    #pragma unroll
    for (int p = 0; p < 8; p++) {
        float4 w0 = ((const float4*)(ep_w + (size_t)(2 * p) * D))[lane];
        float4 w1 = ((const float4*)(ep_w + (size_t)(2 * p + 1) * D))[lane];
        wkp[p][0] = pk(w0.x, w1.x);
        wkp[p][1] = pk(w0.y, w1.y);
        wkp[p][2] = pk(w0.z, w1.z);
        wkp[p][3] = pk(w0.w, w1.w);
    }
    float4 bb = ((const float4*)ep_b)[lane];

    int beg = g_off[v], end = g_off[v + 1];
    int myin = g_flags[v] & 1;
    float4 ef = make_float4(0.f, 0.f, 0.f, 0.f);
    unsigned long long m01 = 0ull, m23 = 0ull;

    if (myin) {
        int s_nx = (beg < end) ? g_src[beg] : 0;
        for (int e = beg; e < end; e++) {
            int s = s_nx;
            unsigned char fl = g_flags[s];
            if (e + 1 < end) s_nx = g_src[e + 1];
            const ulonglong2* a2 = (const ulonglong2*)(g_eap + (size_t)e * 16);
            ulonglong2 q0 = a2[0], q1 = a2[1], q2 = a2[2], q3 = a2[3];
            unsigned long long t0 = 0ull, t1 = 0ull, t2 = 0ull, t3 = 0ull;
            FMA2(t0, q0.x, wkp[0][0]); FMA2(t1, q0.x, wkp[0][1]); FMA2(t2, q0.x, wkp[0][2]); FMA2(t3, q0.x, wkp[0][3]);
            FMA2(t0, q0.y, wkp[1][0]); FMA2(t1, q0.y, wkp[1][1]); FMA2(t2, q0.y, wkp[1][2]); FMA2(t3, q0.y, wkp[1][3]);
            FMA2(t0, q1.x, wkp[2][0]); FMA2(t1, q1.x, wkp[2][1]); FMA2(t2, q1.x, wkp[2][2]); FMA2(t3, q1.x, wkp[2][3]);
            FMA2(t0, q1.y, wkp[3][0]); FMA2(t1, q1.y, wkp[3][1]); FMA2(t2, q1.y, wkp[3][2]); FMA2(t3, q1.y, wkp[3][3]);
            FMA2(t0, q2.x, wkp[4][0]); FMA2(t1, q2.x, wkp[4][1]); FMA2(t2, q2.x, wkp[4][2]); FMA2(t3, q2.x, wkp[4][3]);
            FMA2(t0, q2.y, wkp[5][0]); FMA2(t1, q2.y, wkp[5][1]); FMA2(t2, q2.y, wkp[5][2]); FMA2(t3, q2.y, wkp[5][3]);
            FMA2(t0, q3.x, wkp[6][0]); FMA2(t1, q3.x, wkp[6][1]); FMA2(t2, q3.x, wkp[6][2]); FMA2(t3, q3.x, wkp[6][3]);
            FMA2(t0, q3.y, wkp[7][0]); FMA2(t1, q3.y, wkp[7][1]); FMA2(t2, q3.y, wkp[7][2]); FMA2(t3, q3.y, wkp[7][3]);
            float2 u0 = upk(t0), u1 = upk(t1), u2 = upk(t2), u3 = upk(t3);
            ef.x += fmaxf(bb.x + u0.x + u0.y, 0.f);
            ef.y += fmaxf(bb.y + u1.x + u1.y, 0.f);
            ef.z += fmaxf(bb.z + u2.x + u2.y, 0.f);
            ef.w += fmaxf(bb.w + u3.x + u3.y, 0.f);
            if ((fl >> 1) & 1) {
                float dms = g_dinvm[s];
                unsigned long long dp = pk(dms, dms);
                ulonglong2 xw2 = ((const ulonglong2*)(g_xw + (size_t)s * D))[lane];
                FMA2(m01, xw2.x, dp);
                FMA2(m23, xw2.y, dp);
            }
        }
    } else {
        for (int e = beg; e < end; e++) {
            const ulonglong2* a2 = (const ulonglong2*)(g_eap + (size_t)e * 16);
            ulonglong2 q0 = a2[0], q1 = a2[1], q2 = a2[2], q3 = a2[3];
            unsigned long long t0 = 0ull, t1 = 0ull, t2 = 0ull, t3 = 0ull;
            FMA2(t0, q0.x, wkp[0][0]); FMA2(t1, q0.x, wkp[0][1]); FMA2(t2, q0.x, wkp[0][2]); FMA2(t3, q0.x, wkp[0][3]);
            FMA2(t0, q0.y, wkp[1][0]); FMA2(t1, q0.y, wkp[1][1]); FMA2(t2, q0.y, wkp[1][2]); FMA2(t3, q0.y, wkp[1][3]);
            FMA2(t0, q1.x, wkp[2][0]); FMA2(t1, q1.x, wkp[2][1]); FMA2(t2, q1.x, wkp[2][2]); FMA2(t3, q1.x, wkp[2][3]);
            FMA2(t0, q1.y, wkp[3][0]); FMA2(t1, q1.y, wkp[3][1]); FMA2(t2, q1.y, wkp[3][2]); FMA2(t3, q1.y, wkp[3][3]);
            FMA2(t0, q2.x, wkp[4][0]); FMA2(t1, q2.x, wkp[4][1]); FMA2(t2, q2.x, wkp[4][2]); FMA2(t3, q2.x, wkp[4][3]);
            FMA2(t0, q2.y, wkp[5][0]); FMA2(t1, q2.y, wkp[5][1]); FMA2(t2, q2.y, wkp[5][2]); FMA2(t3, q2.y, wkp[5][3]);
            FMA2(t0, q3.x, wkp[6][0]); FMA2(t1, q3.x, wkp[6][1]); FMA2(t2, q3.x, wkp[6][2]); FMA2(t3, q3.x, wkp[6][3]);
            FMA2(t0, q3.y, wkp[7][0]); FMA2(t1, q3.y, wkp[7][1]); FMA2(t2, q3.y, wkp[7][2]); FMA2(t3, q3.y, wkp[7][3]);
            float2 u0 = upk(t0), u1 = upk(t1), u2 = upk(t2), u3 = upk(t3);
            ef.x += fmaxf(bb.x + u0.x + u0.y, 0.f);
            ef.y += fmaxf(bb.y + u1.x + u1.y, 0.f);
            ef.z += fmaxf(bb.z + u2.x + u2.y, 0.f);
            ef.w += fmaxf(bb.w + u3.x + u3.y, 0.f);
        }
    }
    float dm = g_dinvm[v];
    float2 mA = upk(m01), mB = upk(m23);
    float4 cb = ((const float4*)conv_b)[lane];
    float4 xwv = ((const float4*)(g_xw + (size_t)v * D))[lane];
    float sc = dm * dm;
    float4 o;
    o.x = fmaxf(cb.x + xwv.x * sc + dm * mA.x + ef.x, 0.f);
    o.y = fmaxf(cb.y + xwv.y * sc + dm * mA.y + ef.y, 0.f);
    o.z = fmaxf(cb.z + xwv.z * sc + dm * mB.x + ef.z, 0.f);
    o.w = fmaxf(cb.w + xwv.w * sc + dm * mB.y + ef.w, 0.f);
    ((float4*)(out + (size_t)v * D))[lane] = o;
}

// ---------------- launch ----------------
extern "C" void kernel_launch(void* const* d_in, const int* in_sizes, int n_in,
                              void* d_out, int out_size)
{
    const float* x      = (const float*)d_in[0];
    const int*   ei     = (const int*)  d_in[1];
    const float* ea     = (const float*)d_in[2];
    const float* u_in   = (const float*)d_in[3];
    const float* u_out  = (const float*)d_in[4];
    const float* ln_g   = (const float*)d_in[5];
    const float* ln_b   = (const float*)d_in[6];
    const float* conv_w = (const float*)d_in[7];
    const float* conv_b = (const float*)d_in[8];
    const float* ep_w   = (const float*)d_in[9];
    const float* ep_b   = (const float*)d_in[10];
    const float* ia1_w  = (const float*)d_in[11];
    const float* ia1_b  = (const float*)d_in[12];
    const float* ia2_w  = (const float*)d_in[13];
    const float* ia2_b  = (const float*)d_in[14];
    const float* oa1_w  = (const float*)d_in[15];
    const float* oa1_b  = (const float*)d_in[16];
    const float* oa2_w  = (const float*)d_in[17];
    const float* oa2_b  = (const float*)d_in[18];

    int n = in_sizes[0] / D;       // 50000
    int e = in_sizes[1] / 2;       // 800000
    float* out = (float*)d_out;
    int nb8 = (n + 7) / 8;

    k_init<<<(n + 255) / 256, 256>>>(n);
    k_deg1<<<(e + 1023) / 1024, 256>>>(ei, e);
    k_scan_ln<<<149, 1024>>>(x, ln_g, ln_b, ia1_w, oa1_w, n, e);
    k_fill<<<(e + 1023) / 1024, 256>>>(ei, ea, e);
    k_gemm<<<(n + 63) / 64, 256>>>(conv_w, n);
    k_gather1<<<nb8, 256>>>(ia1_b, oa1_b, ia2_w, oa2_w, n);
    k_gather2<<<nb8, 256>>>(u_in, u_out, ia2_b, oa2_b, n);
    k_degm<<<nb8, 256>>>(n);
    k_final<<<nb8, 256>>>(ep_w, ep_b, conv_b, out, n);
}

// round 8
// speedup vs baseline: 1.4113x; 1.4113x over previous
#include <cuda_runtime.h>
#include <cuda_bf16.h>
#include <cstdint>

#define NMAX 50000
#define EMAX 800000
#define D 128

// ---------------- f32x2 packed helpers ----------------
#define FMA2(d, a, b) \
    asm("fma.rn.f32x2 %0, %1, %2, %0;" : "+l"(d) : "l"(a), "l"(b))

__device__ __forceinline__ unsigned long long pk(float lo, float hi) {
    unsigned long long r;
    asm("mov.b64 %0, {%1, %2};" : "=l"(r) : "f"(lo), "f"(hi));
    return r;
}
__device__ __forceinline__ float2 upk(unsigned long long v) {
    float lo, hi;
    asm("mov.b64 {%0, %1}, %2;" : "=f"(lo), "=f"(hi) : "l"(v));
    return make_float2(lo, hi);
}

// ---------------- device scratch ----------------
__device__ float g_xn[NMAX * D];        // layernormed x
__device__ float g_xw1[NMAX * 32];      // action layer1 projections, pre-scaled by dinv1
__device__ float g_acc1[NMAX * 32];     // scatter accumulator layer1
__device__ float g_t2[NMAX * 4];        // layer2 projections pre-scaled by dinv1
__device__ float g_acc2[NMAX * 4];      // scatter accumulator layer2
__device__ float g_dinv1[NMAX];
__device__ int   g_deg1[NMAX];
__device__ int   g_degm[NMAX];
__device__ float g_dinvm[NMAX];
__device__ unsigned char g_flags[NMAX]; // bit0 = in0, bit1 = out0
__device__ float g_xws[NMAX * D];       // (xn @ conv_w) * dinvm
__device__ int2  g_act[EMAX];           // compacted active edges (src,dst)
__device__ int   g_nact;

// vector reduction into global (sm_90+)
__device__ __forceinline__ void red4(float* p, float4 v) {
    asm volatile("red.global.add.v4.f32 [%0], {%1,%2,%3,%4};"
                 :: "l"(p), "f"(v.x), "f"(v.y), "f"(v.z), "f"(v.w) : "memory");
}

// ---------------- kernels ----------------

__global__ void k_init(int n) {
    int idx = blockIdx.x * blockDim.x + threadIdx.x;
    if (idx < n * 32) g_acc1[idx] = 0.f;
    if (idx < n * 4)  g_acc2[idx] = 0.f;
    if (idx < n)      { g_deg1[idx] = 0; g_degm[idx] = 0; }
    if (idx == 0)     g_nact = 0;
}

__global__ void k_deg1(const int* __restrict__ ei, int e_cnt) {
    int e = blockIdx.x * blockDim.x + threadIdx.x;
    if (e >= e_cnt) return;
    atomicAdd(&g_deg1[ei[e_cnt + e]], 1);
}

// LayerNorm + both action-net layer-1 projections (fused).
__global__ __launch_bounds__(256) void k_ln_proj(
    const float* __restrict__ x, const float* __restrict__ ln_g, const float* __restrict__ ln_b,
    const float* __restrict__ ia1_w, const float* __restrict__ oa1_w, int n)
{
    __shared__ float sW[D * 32];
    __shared__ float sxn[8][D];
    int tid = threadIdx.x;
    for (int i = tid; i < D * 32; i += 256) {
        int k = i >> 5, j = i & 31;
        sW[i] = (j < 16) ? ia1_w[k * 16 + j] : oa1_w[k * 16 + (j - 16)];
    }
    __syncthreads();
    int warp = tid >> 5, lane = tid & 31;
    int nwarps = gridDim.x * 8;
    for (int v = blockIdx.x * 8 + warp; v < n; v += nwarps) {
        float4 xv = ((const float4*)(x + (size_t)v * D))[lane];
        float s1 = xv.x + xv.y + xv.z + xv.w;
        float s2 = xv.x * xv.x + xv.y * xv.y + xv.z * xv.z + xv.w * xv.w;
        #pragma unroll
        for (int o = 16; o; o >>= 1) {
            s1 += __shfl_xor_sync(0xffffffffu, s1, o);
            s2 += __shfl_xor_sync(0xffffffffu, s2, o);
        }
        float mu = s1 * (1.f / 128.f);
        float var = s2 * (1.f / 128.f) - mu * mu;
        float rs = rsqrtf(var + 1e-5f);
        float4 g4 = ((const float4*)ln_g)[lane];
        float4 b4 = ((const float4*)ln_b)[lane];
        float4 o4;
        o4.x = (xv.x - mu) * rs * g4.x + b4.x;
        o4.y = (xv.y - mu) * rs * g4.y + b4.y;
        o4.z = (xv.z - mu) * rs * g4.z + b4.z;
        o4.w = (xv.w - mu) * rs * g4.w + b4.w;
        ((float4*)(g_xn + (size_t)v * D))[lane] = o4;
        ((float4*)sxn[warp])[lane] = o4;
        __syncwarp();
        float dinv = rsqrtf((float)g_deg1[v] + 1.0f);
        float acc = 0.f;
        const float* sx = sxn[warp];
        #pragma unroll 16
        for (int k = 0; k < D; k++) acc = fmaf(sx[k], sW[k * 32 + lane], acc);
        g_xw1[v * 32 + lane] = acc * dinv;
        if (lane == 0) g_dinv1[v] = dinv;
        __syncwarp();
    }
}

// scatter layer-1 messages: 8 float4 chunks per edge
__global__ void k_scatter1(const int* __restrict__ ei, int e_cnt) {
    int idx = blockIdx.x * blockDim.x + threadIdx.x;
    if (idx >= e_cnt * 8) return;
    int e = idx >> 3, c = idx & 7;
    int s = ei[e], d = ei[e_cnt + e];
    float4 v = *((const float4*)(g_xw1 + (size_t)s * 32) + c);
    red4(g_acc1 + (size_t)d * 32 + c * 4, v);
}

// finalize h (relu) + project to layer2 logits contribution (pre-scaled by dinv1)
__global__ void k_fin1(const float* __restrict__ ia1_b, const float* __restrict__ oa1_b,
                       const float* __restrict__ ia2_w, const float* __restrict__ oa2_w, int n)
{
    int tid = blockIdx.x * blockDim.x + threadIdx.x;
    int v = tid >> 5, lane = tid & 31;
    if (v >= n) return;
    float dinv = g_dinv1[v];
    float xw1s = g_xw1[v * 32 + lane];
    float bias = (lane < 16) ? ia1_b[lane] : oa1_b[lane - 16];
    float h = dinv * g_acc1[v * 32 + lane] + xw1s * dinv + bias;
    h = fmaxf(h, 0.f);
    float w0 = (lane < 16) ? ia2_w[lane * 2] : oa2_w[(lane - 16) * 2];
    float w1 = (lane < 16) ? ia2_w[lane * 2 + 1] : oa2_w[(lane - 16) * 2 + 1];
    float p0 = h * w0, p1 = h * w1;
    #pragma unroll
    for (int o = 8; o; o >>= 1) {
        p0 += __shfl_xor_sync(0xffffffffu, p0, o);
        p1 += __shfl_xor_sync(0xffffffffu, p1, o);
    }
    if (lane == 0)  { g_t2[v * 4 + 0] = p0 * dinv; g_t2[v * 4 + 1] = p1 * dinv; }
    if (lane == 16) { g_t2[v * 4 + 2] = p0 * dinv; g_t2[v * 4 + 3] = p1 * dinv; }
}

__global__ void k_scatter2(const int* __restrict__ ei, int e_cnt) {
    int e = blockIdx.x * blockDim.x + threadIdx.x;
    if (e >= e_cnt) return;
    int s = ei[e], d = ei[e_cnt + e];
    float4 t = *(const float4*)(g_t2 + (size_t)s * 4);
    red4(g_acc2 + (size_t)d * 4, t);
}

__global__ void k_gumbel(const float* __restrict__ u_in, const float* __restrict__ u_out,
                         const float* __restrict__ ia2_b, const float* __restrict__ oa2_b, int n)
{
    int v = blockIdx.x * blockDim.x + threadIdx.x;
    if (v >= n) return;
    float dinv = g_dinv1[v];
    float li0 = dinv * g_acc2[v * 4 + 0] + g_t2[v * 4 + 0] * dinv + ia2_b[0];
    float li1 = dinv * g_acc2[v * 4 + 1] + g_t2[v * 4 + 1] * dinv + ia2_b[1];
    float lo0 = dinv * g_acc2[v * 4 + 2] + g_t2[v * 4 + 2] * dinv + oa2_b[0];
    float lo1 = dinv * g_acc2[v * 4 + 3] + g_t2[v * 4 + 3] * dinv + oa2_b[1];
    float gi0 = -logf(-logf(u_in[v * 2 + 0] + 1e-10f) + 1e-10f);
    float gi1 = -logf(-logf(u_in[v * 2 + 1] + 1e-10f) + 1e-10f);
    float go0 = -logf(-logf(u_out[v * 2 + 0] + 1e-10f) + 1e-10f);
    float go1 = -logf(-logf(u_out[v * 2 + 1] + 1e-10f) + 1e-10f);
    int in0  = (li0 + gi0 >= li1 + gi1) ? 1 : 0;
    int out0 = (lo0 + go0 >= lo1 + go1) ? 1 : 0;
    g_flags[v] = (unsigned char)(in0 | (out0 << 1));
}

// weighted degree + warp-aggregated compaction of active edges
__global__ void k_compact(const int* __restrict__ ei, int e_cnt) {
    int e = blockIdx.x * blockDim.x + threadIdx.x;
    int lane = threadIdx.x & 31;
    int s = 0, d = 0, act = 0;
    if (e < e_cnt) {
        s = ei[e]; d = ei[e_cnt + e];
        act = (g_flags[d] & 1) && ((g_flags[s] >> 1) & 1);
    }
    unsigned m = __ballot_sync(0xffffffffu, act);
    if (m) {
        int leader = __ffs(m) - 1;
        int base = 0;
        if (lane == leader) base = atomicAdd(&g_nact, __popc(m));
        base = __shfl_sync(0xffffffffu, base, leader);
        if (act) {
            int r = __popc(m & ((1u << lane) - 1));
            g_act[base + r] = make_int2(s, d);
            atomicAdd(&g_degm[d], 1);
        }
    }
}

// xw = xn @ conv_w (f32x2 packed); dinvm computed in epilogue;
// store xws = xw*dinvm; seed d_out = xws*dinvm + conv_b.
__global__ __launch_bounds__(256) void k_gemm(const float* __restrict__ conv_w,
                                              const float* __restrict__ conv_b,
                                              float* __restrict__ out, int n)
{
    __shared__ float sA[64][32];
    __shared__ ulonglong2 sB[16 * 2 * 32];
    float* sBf = (float*)sB;
    int tid = threadIdx.x;
    int lane = tid & 31, warp = tid >> 5;
    int row0 = blockIdx.x * 64, rb = warp * 8;
    unsigned long long acc[8][4];
    #pragma unroll
    for (int r = 0; r < 8; r++)
        #pragma unroll
        for (int c = 0; c < 4; c++) acc[r][c] = 0ull;

    for (int kc = 0; kc < D; kc += 32) {
        for (int i = tid; i < 1024; i += 256) {
            int kk = i >> 5, c = i & 31;
            float4 w = ((const float4*)(conv_w + (size_t)(kc + kk) * D))[c];
            int p = kk >> 1, par = kk & 1;
            int b0i = (((p * 2 + 0) * 32 + c) << 2);
            int b1i = (((p * 2 + 1) * 32 + c) << 2);
            sBf[b0i + par]     = w.x;
            sBf[b0i + 2 + par] = w.y;
            sBf[b1i + par]     = w.z;
            sBf[b1i + 2 + par] = w.w;
        }
        for (int i = tid; i < 512; i += 256) {
            int r = i >> 3, c4 = i & 7;
            float4 vv = make_float4(0.f, 0.f, 0.f, 0.f);
            if (row0 + r < n)
                vv = ((const float4*)(g_xn + (size_t)(row0 + r) * D + kc))[c4];
            sA[r][c4 * 4 + 0] = vv.x; sA[r][c4 * 4 + 1] = vv.y;
            sA[r][c4 * 4 + 2] = vv.z; sA[r][c4 * 4 + 3] = vv.w;
        }
        __syncthreads();
        #pragma unroll
        for (int p = 0; p < 16; p++) {
            ulonglong2 b0 = sB[(p * 2 + 0) * 32 + lane];
            ulonglong2 b1 = sB[(p * 2 + 1) * 32 + lane];
            #pragma unroll
            for (int r = 0; r < 8; r++) {
                unsigned long long ap = *(const unsigned long long*)&sA[rb + r][2 * p];
                FMA2(acc[r][0], ap, b0.x);
                FMA2(acc[r][1], ap, b0.y);
                FMA2(acc[r][2], ap, b1.x);
                FMA2(acc[r][3], ap, b1.y);
            }
        }
        __syncthreads();
    }
    float4 bb = ((const float4*)conv_b)[lane];
    #pragma unroll
    for (int r = 0; r < 8; r++) {
        int v = row0 + rb + r;
        if (v < n) {
            float dm = rsqrtf((float)g_degm[v] + 1.0f);   // fused dinvm
            if (lane == 0) g_dinvm[v] = dm;
            float2 u0 = upk(acc[r][0]), u1 = upk(acc[r][1]);
            float2 u2 = upk(acc[r][2]), u3 = upk(acc[r][3]);
            float4 w = make_float4((u0.x + u0.y) * dm, (u1.x + u1.y) * dm,
                                   (u2.x + u2.y) * dm, (u3.x + u3.y) * dm);
            ((float4*)(g_xws + (size_t)v * D))[lane] = w;
            float4 o = make_float4(w.x * dm + bb.x, w.y * dm + bb.y,
                                   w.z * dm + bb.z, w.w * dm + bb.w);
            ((float4*)(out + (size_t)v * D))[lane] = o;
        }
    }
}

// main conv scatter over compacted active edges (one warp per edge, grid-stride)
__global__ void k_scatter_main(float* __restrict__ out) {
    int gw = (blockIdx.x * blockDim.x + threadIdx.x) >> 5;
    int lane = threadIdx.x & 31;
    int nw = (gridDim.x * blockDim.x) >> 5;
    int nact = g_nact;
    for (int e = gw; e < nact; e += nw) {
        int2 sd = g_act[e];
        float dm = g_dinvm[sd.y];
        float4 v = ((const float4*)(g_xws + (size_t)sd.x * D))[lane];
        v.x *= dm; v.y *= dm; v.z *= dm; v.w *= dm;
        red4(out + (size_t)sd.y * D + lane * 4, v);
    }
}

// edge_features = relu(edge_attr @ ep_w + ep_b), scattered into out.
// Weights stationary in registers as f32x2 k-pairs; grid-stride warps.
__global__ __launch_bounds__(256) void k_edgefeat(const int* __restrict__ ei,
                                                  const float* __restrict__ ea,
                                                  const float* __restrict__ ep_w,
                                                  const float* __restrict__ ep_b,
                                                  float* __restrict__ out, int e_cnt)
{
    int lane = threadIdx.x & 31;
    unsigned long long wkp[8][4];
    #pragma unroll
    for (int p = 0; p < 8; p++) {
        float4 w0 = ((const float4*)(ep_w + (size_t)(2 * p) * D))[lane];
        float4 w1 = ((const float4*)(ep_w + (size_t)(2 * p + 1) * D))[lane];
        wkp[p][0] = pk(w0.x, w1.x);
        wkp[p][1] = pk(w0.y, w1.y);
        wkp[p][2] = pk(w0.z, w1.z);
        wkp[p][3] = pk(w0.w, w1.w);
    }
    float4 bb = ((const float4*)ep_b)[lane];

    int gw = (blockIdx.x * blockDim.x + threadIdx.x) >> 5;
    int nw = (gridDim.x * blockDim.x) >> 5;
    for (int e = gw; e < e_cnt; e += nw) {
        int d = ei[e_cnt + e];
        const ulonglong2* a2 = (const ulonglong2*)(ea + (size_t)e * 16);
        ulonglong2 q0 = a2[0], q1 = a2[1], q2 = a2[2], q3 = a2[3];
        unsigned long long t0 = 0ull, t1 = 0ull, t2 = 0ull, t3 = 0ull;
        FMA2(t0, q0.x, wkp[0][0]); FMA2(t1, q0.x, wkp[0][1]); FMA2(t2, q0.x, wkp[0][2]); FMA2(t3, q0.x, wkp[0][3]);
        FMA2(t0, q0.y, wkp[1][0]); FMA2(t1, q0.y, wkp[1][1]); FMA2(t2, q0.y, wkp[1][2]); FMA2(t3, q0.y, wkp[1][3]);
        FMA2(t0, q1.x, wkp[2][0]); FMA2(t1, q1.x, wkp[2][1]); FMA2(t2, q1.x, wkp[2][2]); FMA2(t3, q1.x, wkp[2][3]);
        FMA2(t0, q1.y, wkp[3][0]); FMA2(t1, q1.y, wkp[3][1]); FMA2(t2, q1.y, wkp[3][2]); FMA2(t3, q1.y, wkp[3][3]);
        FMA2(t0, q2.x, wkp[4][0]); FMA2(t1, q2.x, wkp[4][1]); FMA2(t2, q2.x, wkp[4][2]); FMA2(t3, q2.x, wkp[4][3]);
        FMA2(t0, q2.y, wkp[5][0]); FMA2(t1, q2.y, wkp[5][1]); FMA2(t2, q2.y, wkp[5][2]); FMA2(t3, q2.y, wkp[5][3]);
        FMA2(t0, q3.x, wkp[6][0]); FMA2(t1, q3.x, wkp[6][1]); FMA2(t2, q3.x, wkp[6][2]); FMA2(t3, q3.x, wkp[6][3]);
        FMA2(t0, q3.y, wkp[7][0]); FMA2(t1, q3.y, wkp[7][1]); FMA2(t2, q3.y, wkp[7][2]); FMA2(t3, q3.y, wkp[7][3]);
        float2 u0 = upk(t0), u1 = upk(t1), u2 = upk(t2), u3 = upk(t3);
        float4 r;
        r.x = fmaxf(bb.x + u0.x + u0.y, 0.f);
        r.y = fmaxf(bb.y + u1.x + u1.y, 0.f);
        r.z = fmaxf(bb.z + u2.x + u2.y, 0.f);
        r.w = fmaxf(bb.w + u3.x + u3.y, 0.f);
        red4(out + (size_t)d * D + lane * 4, r);
    }
}

__global__ void k_relu(float* __restrict__ out, int n4) {
    int i = blockIdx.x * blockDim.x + threadIdx.x;
    if (i >= n4) return;
    float4 v = ((float4*)out)[i];
    v.x = fmaxf(v.x, 0.f); v.y = fmaxf(v.y, 0.f);
    v.z = fmaxf(v.z, 0.f); v.w = fmaxf(v.w, 0.f);
    ((float4*)out)[i] = v;
}

// ---------------- launch ----------------
extern "C" void kernel_launch(void* const* d_in, const int* in_sizes, int n_in,
                              void* d_out, int out_size)
{
    const float* x      = (const float*)d_in[0];
    const int*   ei     = (const int*)  d_in[1];
    const float* ea     = (const float*)d_in[2];
    const float* u_in   = (const float*)d_in[3];
    const float* u_out  = (const float*)d_in[4];
    const float* ln_g   = (const float*)d_in[5];
    const float* ln_b   = (const float*)d_in[6];
    const float* conv_w = (const float*)d_in[7];
    const float* conv_b = (const float*)d_in[8];
    const float* ep_w   = (const float*)d_in[9];
    const float* ep_b   = (const float*)d_in[10];
    const float* ia1_w  = (const float*)d_in[11];
    const float* ia1_b  = (const float*)d_in[12];
    const float* ia2_w  = (const float*)d_in[13];
    const float* ia2_b  = (const float*)d_in[14];
    const float* oa1_w  = (const float*)d_in[15];
    const float* oa1_b  = (const float*)d_in[16];
    const float* oa2_w  = (const float*)d_in[17];
    const float* oa2_b  = (const float*)d_in[18];

    int n = in_sizes[0] / D;       // 50000
    int e = in_sizes[1] / 2;       // 800000
    float* out = (float*)d_out;

    k_init<<<(n * 32 + 255) / 256, 256>>>(n);
    k_deg1<<<(e + 255) / 256, 256>>>(ei, e);
    k_ln_proj<<<592, 256>>>(x, ln_g, ln_b, ia1_w, oa1_w, n);
    k_scatter1<<<(e * 8 + 255) / 256, 256>>>(ei, e);
    k_fin1<<<(n * 32 + 255) / 256, 256>>>(ia1_b, oa1_b, ia2_w, oa2_w, n);
    k_scatter2<<<(e + 255) / 256, 256>>>(ei, e);
    k_gumbel<<<(n + 255) / 256, 256>>>(u_in, u_out, ia2_b, oa2_b, n);
    k_compact<<<(e + 255) / 256, 256>>>(ei, e);
    k_gemm<<<(n + 63) / 64, 256>>>(conv_w, conv_b, out, n);
    k_scatter_main<<<1184, 256>>>(out);
    k_edgefeat<<<1184, 256>>>(ei, ea, ep_w, ep_b, out, e);
    k_relu<<<(n * 32 + 255) / 256, 256>>>(out, n * 32);
}